// round 11
// baseline (speedup 1.0000x reference)
#include <cuda_runtime.h>

#define IMG_W 1242
#define IMG_H 375
#define IMG_HW (IMG_H * IMG_W)
#define BMAX 32
#define WPAIRS 621       // IMG_W / 2
#define WTILES2 20       // ceil(621/32)
#define NBORDER (2 * IMG_W + 2 * (IMG_H - 2))   // 3230 border pixels

// ---- scratch (device globals: allocation-free, zero-initialized at load) ----
__device__ double g_acc[2];   // [0] sum err (pc loss), [1] sum derr (depth loss)
__device__ unsigned g_done;   // completion counter for k2 final fold
__device__ unsigned long long g_keys[(size_t)BMAX * IMG_HW];  // (n<<32)|float_bits(Z); 0 = empty

// ---------------------------------------------------------------------------
// K1: per-point transform (pred & gt), pc err, project + scatter.
// Border pixels (the provably-hot clip targets) aggregate through a 3230-entry
// shared table per block; interior pixels go straight to global atomics.
// ---------------------------------------------------------------------------
__global__ void __launch_bounds__(512) k1_points(const float4* __restrict__ pts,
                                                 const float* __restrict__ pr_t,
                                                 const float* __restrict__ pr_r,
                                                 const float* __restrict__ gt_rt,   // B x 16
                                                 const float* __restrict__ kmat,    // 9
                                                 int B, int N) {
    __shared__ unsigned long long sB[NBORDER];   // 25.8 KB border table
    __shared__ float sMp[12];
    __shared__ float sMg[16];
    __shared__ float shred[16];

    int tid = blockIdx.x * blockDim.x + threadIdx.x;
    int b = tid / N;   // blocks never straddle batches (N % 512 == 0)

    if (threadIdx.x == 0) {
        float rx = pr_r[3*b+0], ry = pr_r[3*b+1], rz = pr_r[3*b+2];
        float th2 = rx*rx + ry*ry + rz*rz;
        float th  = sqrtf(th2);
        float A   = sinf(th) / th;
        float Bc  = (1.0f - cosf(th)) / th2;
        sMp[0]  = 1.f + Bc*(rx*rx - th2); sMp[1]  = -A*rz + Bc*rx*ry;       sMp[2]  =  A*ry + Bc*rx*rz;       sMp[3]  = pr_t[3*b+0];
        sMp[4]  =  A*rz + Bc*rx*ry;       sMp[5]  = 1.f + Bc*(ry*ry - th2); sMp[6]  = -A*rx + Bc*ry*rz;       sMp[7]  = pr_t[3*b+1];
        sMp[8]  = -A*ry + Bc*rx*rz;       sMp[9]  =  A*rx + Bc*ry*rz;       sMp[10] = 1.f + Bc*(rz*rz - th2); sMp[11] = pr_t[3*b+2];
    }
    if (threadIdx.x < 16) sMg[threadIdx.x] = gt_rt[b * 16 + threadIdx.x];
    for (int i = threadIdx.x; i < NBORDER; i += 512) sB[i] = 0ull;
    __syncthreads();

    float err = 0.f;
    bool ok = (tid < B * N);
    float X = 0.f, Y = 0.f, Zc = 0.f;
    if (ok) {
        float4 p = pts[tid];
        X  = fmaf(sMp[0], p.x, fmaf(sMp[1], p.y, fmaf(sMp[2],  p.z, sMp[3])));
        Y  = fmaf(sMp[4], p.x, fmaf(sMp[5], p.y, fmaf(sMp[6],  p.z, sMp[7])));
        Zc = fmaf(sMp[8], p.x, fmaf(sMp[9], p.y, fmaf(sMp[10], p.z, sMp[11])));
        float Xg = fmaf(sMg[0], p.x, fmaf(sMg[1], p.y, fmaf(sMg[2],  p.z, sMg[3])));
        float Yg = fmaf(sMg[4], p.x, fmaf(sMg[5], p.y, fmaf(sMg[6],  p.z, sMg[7])));
        float Zg = fmaf(sMg[8], p.x, fmaf(sMg[9], p.y, fmaf(sMg[10], p.z, sMg[11])));
        float dx = X - Xg, dy = Y - Yg, dz = Zc - Zg;
        err = sqrtf(dx*dx + dy*dy + dz*dz);
    }

    bool act = ok && (Zc > 0.f);
    unsigned ballot = __ballot_sync(0xffffffffu, act);
    if (act) {
        float fx = kmat[0], cx = kmat[2], fy = kmat[4], cy = kmat[5];
        float px = (fx * X + cx * Zc) / Zc;
        float py = (fy * Y + cy * Zc) / Zc;
        px = fminf(fmaxf(px, 0.f), (float)(IMG_W - 1));
        py = fminf(fmaxf(py, 0.f), (float)(IMG_H - 1));
        int xi = (int)px, yi = (int)py;
        unsigned n = (unsigned)(tid - b * N);
        unsigned long long key = ((unsigned long long)n << 32) |
                                 (unsigned long long)__float_as_uint(Zc);
        bool border = (yi == 0) | (yi == IMG_H - 1) | (xi == 0) | (xi == IMG_W - 1);
        unsigned pix = (unsigned)(yi * IMG_W + xi);
        // warp-aggregate by pixel: max point-index == max key within a group
        unsigned peers = __match_any_sync(ballot, pix | (border ? 0x80000000u : 0u));
        unsigned gmax  = __reduce_max_sync(peers, n);
        if (n == gmax) {
            if (border) {
                int bidx;
                if (yi == 0)                bidx = xi;
                else if (yi == IMG_H - 1)   bidx = IMG_W + xi;
                else if (xi == 0)           bidx = 2 * IMG_W + (yi - 1);
                else                        bidx = 2 * IMG_W + (IMG_H - 2) + (yi - 1);
                atomicMax(&sB[bidx], key);
            } else {
                atomicMax(&g_keys[(size_t)b * IMG_HW + pix], key);
            }
        }
    }

    // block reduce pc err -> one double atomic per block
    #pragma unroll
    for (int o = 16; o > 0; o >>= 1) err += __shfl_down_sync(0xffffffffu, err, o);
    if ((threadIdx.x & 31) == 0) shred[threadIdx.x >> 5] = err;
    __syncthreads();
    if (threadIdx.x == 0) {
        float t = 0.f;
        #pragma unroll
        for (int j = 0; j < 16; j++) t += shred[j];
        atomicAdd(&g_acc[0], (double)t);
    }

    // flush border table (one global atomic per touched border pixel per block)
    size_t gbase = (size_t)b * IMG_HW;
    for (int i = threadIdx.x; i < NBORDER; i += 512) {
        unsigned long long k = sB[i];
        if (k) {
            int xi, yi;
            if (i < IMG_W)                        { yi = 0;          xi = i; }
            else if (i < 2 * IMG_W)               { yi = IMG_H - 1;  xi = i - IMG_W; }
            else if (i < 2 * IMG_W + (IMG_H - 2)) { xi = 0;          yi = i - 2 * IMG_W + 1; }
            else                                  { xi = IMG_W - 1;  yi = i - 2 * IMG_W - (IMG_H - 2) + 1; }
            atomicMax(&g_keys[gbase + yi * IMG_W + xi], k);
        }
    }
}

// ---------------------------------------------------------------------------
// K2: depth-map loss. Each thread owns TWO adjacent columns (vectorized
// ulonglong2 / float2 loads). Block = 32 col-pairs x 16 h-slices (512 thr,
// grid 640 -> ~full occupancy). Scrubs touched keys; streaming loads.
// Last block folds the final combine and resets accumulators for replay.
// ---------------------------------------------------------------------------
__global__ void __launch_bounds__(512) k2_depth(const float* __restrict__ gt_depth,
                                                const float* __restrict__ gt_t,
                                                const float* __restrict__ gt_r,
                                                const float* __restrict__ pr_t,
                                                const float* __restrict__ pr_r,
                                                float* __restrict__ out,
                                                int B, int N) {
    int b  = blockIdx.x / WTILES2;
    int tw = blockIdx.x - b * WTILES2;
    int wp = tw * 32 + threadIdx.x;   // column-pair index

    float s0 = 0.f, s1 = 0.f;
    if (wp < WPAIRS) {
        size_t base = (size_t)b * IMG_HW + 2 * wp;   // even -> 16B aligned
        #pragma unroll 4
        for (int h = threadIdx.y; h < IMG_H; h += 16) {
            size_t off = base + (size_t)h * IMG_W;
            ulonglong2 kk = __ldcs((const ulonglong2*)&g_keys[off]);
            float2 gd = __ldcs((const float2*)&gt_depth[off]);
            float d0 = 0.f, d1 = 0.f;
            if (kk.x) d0 = __uint_as_float((unsigned)kk.x);
            if (kk.y) d1 = __uint_as_float((unsigned)kk.y);
            if (kk.x | kk.y) {
                ulonglong2 z; z.x = 0ull; z.y = 0ull;
                __stcs((ulonglong2*)&g_keys[off], z);
            }
            float f0 = d0 - gd.x, f1 = d1 - gd.y;
            s0 = fmaf(f0, f0, s0);
            s1 = fmaf(f1, f1, s1);
        }
    }

    __shared__ float sh0[16][33];
    __shared__ float sh1[16][33];
    sh0[threadIdx.y][threadIdx.x] = s0;
    sh1[threadIdx.y][threadIdx.x] = s1;
    __syncthreads();
    if (threadIdx.y == 0) {
        float t0 = 0.f, t1 = 0.f;
        #pragma unroll
        for (int j = 0; j < 16; j++) { t0 += sh0[j][threadIdx.x]; t1 += sh1[j][threadIdx.x]; }
        float derr = (wp < WPAIRS) ? (sqrtf(t0) + sqrtf(t1)) : 0.f;
        #pragma unroll
        for (int o = 16; o > 0; o >>= 1) derr += __shfl_down_sync(0xffffffffu, derr, o);
        if (threadIdx.x == 0) atomicAdd(&g_acc[1], (double)derr);
    }

    // ---- last-block final combine ----
    __shared__ int is_last;
    __threadfence();
    if (threadIdx.x == 0 && threadIdx.y == 0) {
        unsigned done = atomicAdd(&g_done, 1u);
        is_last = (done == gridDim.x - 1) ? 1 : 0;
    }
    __syncthreads();
    if (is_last && threadIdx.y == 0) {
        // transformation loss (one warp, one lane per batch)
        int lb = threadIdx.x;
        float st = 0.f, sr = 0.f;
        if (lb < B) {
            #pragma unroll
            for (int i = 0; i < 3; i++) {
                float dt = pr_t[3*lb+i] - gt_t[3*lb+i]; st += dt*dt;
                float dr = pr_r[3*lb+i] - gt_r[3*lb+i]; sr += dr*dr;
            }
        }
        #pragma unroll
        for (int o = 16; o > 0; o >>= 1) {
            st += __shfl_down_sync(0xffffffffu, st, o);
            sr += __shfl_down_sync(0xffffffffu, sr, o);
        }
        if (threadIdx.x == 0) {
            double pc_sum = atomicAdd(&g_acc[0], 0.0);
            double de_sum = atomicAdd(&g_acc[1], 0.0);
            float trans = 2.0f * (st / B) + (sr / B);   // TRANS_W=2, ROT_W=1
            float depth = (float)((de_sum / (double)IMG_W) / (double)B);
            float pcl   = (float)((pc_sum / (double)N) / (double)B);
            out[0] = 0.5f * trans + depth + 0.5f * pcl; // (1-PC_W)*trans + DEPTH_W*depth + PC_W*pcl
            out[1] = trans;
            out[2] = depth;
            out[3] = pcl;
            // reset for next graph replay
            g_acc[0] = 0.0;
            g_acc[1] = 0.0;
            g_done = 0u;
        }
    }
}

// ---------------------------------------------------------------------------
extern "C" void kernel_launch(void* const* d_in, const int* in_sizes, int n_in,
                              void* d_out, int out_size) {
    const float4* pts      = (const float4*)d_in[0];
    const float*  gt_t     = (const float*)d_in[1];
    const float*  gt_r     = (const float*)d_in[2];
    const float*  pr_t     = (const float*)d_in[3];
    const float*  pr_r     = (const float*)d_in[4];
    const float*  gt_rt    = (const float*)d_in[5];
    const float*  kmat     = (const float*)d_in[6];
    const float*  gt_depth = (const float*)d_in[7];

    int B = in_sizes[1] / 3;
    int N = in_sizes[0] / (4 * B);

    int npts = B * N;
    k1_points<<<(npts + 511) / 512, 512>>>(pts, pr_t, pr_r, gt_rt, kmat, B, N);

    dim3 blk(32, 16);
    k2_depth<<<B * WTILES2, blk>>>(gt_depth, gt_t, gt_r, pr_t, pr_r, (float*)d_out, B, N);
}